// round 5
// baseline (speedup 1.0000x reference)
#include <cuda_runtime.h>
#include <math.h>

#define NN   10000
#define EE   160000
#define ET   170000
#define FIN  78
#define CC   128
#define HH   10
#define F1   1280
#define GG   64

#define NEG_INF __int_as_float(0xff800000)

// ---------------- scratch (device globals; allocation-free) ----------------
__device__ float g_h1[(size_t)NN * F1];     // x @ W1
__device__ float g_out1[(size_t)NN * F1];   // layer-1 aggregated -> elu in place
__device__ float g_h2[(size_t)NN * CC];     // h1a @ W2
__device__ float g_out2[(size_t)NN * CC];   // layer-2 aggregated -> elu in place
__device__ float g_asrc[NN * HH];
__device__ float g_adst[NN * HH];
__device__ float g_segmax[NN * HH];
__device__ float g_segsum[NN * HH];
__device__ float g_ev[(size_t)ET * HH];     // e -> ex -> alpha
__device__ int   g_src[ET];
__device__ int   g_dst[ET];
__device__ int   g_deg[NN];
__device__ int   g_rowptr[NN + 1];
__device__ int   g_cursor[NN];
__device__ int   g_eid[ET];

// ---------------- helpers ----------------
__device__ __forceinline__ void atomicMaxF(float* addr, float v) {
    if (v >= 0.f) atomicMax((int*)addr, __float_as_int(v));
    else          atomicMin((unsigned int*)addr, __float_as_uint(v));
}

// ---------------- edge prep + CSR build ----------------
__global__ void k_prep_edges(const int* __restrict__ ei) {
    int i = blockIdx.x * blockDim.x + threadIdx.x;
    if (i >= ET) return;
    int s, d;
    if (i < EE) { s = ei[i]; d = ei[EE + i]; }
    else        { s = d = i - EE; }          // self loops
    g_src[i] = s;
    g_dst[i] = d;
}

__global__ void k_zero_deg() {
    int i = blockIdx.x * blockDim.x + threadIdx.x;
    if (i < NN) g_deg[i] = 0;
}

__global__ void k_count() {
    int i = blockIdx.x * blockDim.x + threadIdx.x;
    if (i < ET) atomicAdd(&g_deg[g_dst[i]], 1);
}

__global__ void k_scan() {   // single block, 1024 threads
    __shared__ int sm[1024];
    __shared__ int carry;
    int tid = threadIdx.x;
    if (tid == 0) carry = 0;
    __syncthreads();
    for (int base = 0; base < NN; base += 1024) {
        int i = base + tid;
        int v = (i < NN) ? g_deg[i] : 0;
        sm[tid] = v;
        __syncthreads();
        for (int off = 1; off < 1024; off <<= 1) {
            int t = (tid >= off) ? sm[tid - off] : 0;
            __syncthreads();
            sm[tid] += t;
            __syncthreads();
        }
        if (i < NN) {
            int excl = carry + sm[tid] - v;
            g_rowptr[i] = excl;
            g_cursor[i] = excl;
        }
        __syncthreads();
        if (tid == 0) carry += sm[1023];
        __syncthreads();
    }
    if (tid == 0) g_rowptr[NN] = carry;
}

__global__ void k_scatter() {
    int i = blockIdx.x * blockDim.x + threadIdx.x;
    if (i >= ET) return;
    int pos = atomicAdd(&g_cursor[g_dst[i]], 1);
    g_eid[pos] = i;
}

// ---------------- GEMM (fp32, 64x64 tile, 4x4 per thread) ----------------
__global__ void k_gemm(const float* __restrict__ A, const float* __restrict__ B,
                       float* __restrict__ Cm, int M, int K, int Nn) {
    const int BM = 64, BN = 64, BK = 16;
    __shared__ float As[BK][BM];
    __shared__ float Bs[BK][BN];
    int tid = threadIdx.x;
    int tx = tid & 15, ty = tid >> 4;
    int bm0 = blockIdx.x * BM, bn0 = blockIdx.y * BN;
    float acc[4][4] = {};
    for (int k0 = 0; k0 < K; k0 += BK) {
        for (int t = tid; t < BM * BK; t += 256) {
            int r = t / BK, kk = t - r * BK;
            int gr = bm0 + r, gk = k0 + kk;
            As[kk][r] = (gr < M && gk < K) ? A[(size_t)gr * K + gk] : 0.f;
        }
        for (int t = tid; t < BK * BN; t += 256) {
            int kk = t / BN, c = t - kk * BN;
            int gk = k0 + kk, gc = bn0 + c;
            Bs[kk][c] = (gk < K && gc < Nn) ? B[(size_t)gk * Nn + gc] : 0.f;
        }
        __syncthreads();
        #pragma unroll
        for (int k = 0; k < BK; k++) {
            float a[4], b[4];
            #pragma unroll
            for (int i = 0; i < 4; i++) a[i] = As[k][ty * 4 + i];
            #pragma unroll
            for (int j = 0; j < 4; j++) b[j] = Bs[k][tx * 4 + j];
            #pragma unroll
            for (int i = 0; i < 4; i++)
                #pragma unroll
                for (int j = 0; j < 4; j++) acc[i][j] += a[i] * b[j];
        }
        __syncthreads();
    }
    #pragma unroll
    for (int i = 0; i < 4; i++) {
        int gr = bm0 + ty * 4 + i;
        if (gr >= M) continue;
        #pragma unroll
        for (int j = 0; j < 4; j++) {
            int gc = bn0 + tx * 4 + j;
            if (gc >= Nn) continue;
            Cm[(size_t)gr * Nn + gc] = acc[i][j];
        }
    }
}

// ---------------- attention dot products per node ----------------
__global__ void k_alphadot(const float* __restrict__ h,
                           const float* __restrict__ wsrc,
                           const float* __restrict__ wdst,
                           float* __restrict__ asrc, float* __restrict__ adst,
                           int H) {
    int n = blockIdx.x;
    int wid = threadIdx.x >> 5, lane = threadIdx.x & 31;
    if (wid >= H) return;
    const float* hr = h + ((size_t)n * H + wid) * CC;
    const float* ws = wsrc + wid * CC;
    const float* wd = wdst + wid * CC;
    float s1 = 0.f, s2 = 0.f;
    for (int c = lane; c < CC; c += 32) {
        float v = hr[c];
        s1 += v * ws[c];
        s2 += v * wd[c];
    }
    #pragma unroll
    for (int o = 16; o > 0; o >>= 1) {
        s1 += __shfl_down_sync(0xffffffff, s1, o);
        s2 += __shfl_down_sync(0xffffffff, s2, o);
    }
    if (lane == 0) {
        asrc[n * H + wid] = s1;
        adst[n * H + wid] = s2;
    }
}

__global__ void k_initseg(int n) {
    int i = blockIdx.x * blockDim.x + threadIdx.x;
    if (i < n) { g_segmax[i] = NEG_INF; g_segsum[i] = 0.f; }
}

// ---------------- edge softmax ----------------
__global__ void k_edge_e(int H) {
    int idx = blockIdx.x * blockDim.x + threadIdx.x;
    if (idx >= ET * H) return;
    int e = idx / H, h = idx - e * H;
    float v = g_asrc[g_src[e] * H + h] + g_adst[g_dst[e] * H + h];
    v = (v >= 0.f) ? v : 0.2f * v;     // leaky_relu 0.2
    g_ev[idx] = v;
    atomicMaxF(&g_segmax[g_dst[e] * H + h], v);
}

__global__ void k_edge_exp(int H) {
    int idx = blockIdx.x * blockDim.x + threadIdx.x;
    if (idx >= ET * H) return;
    int e = idx / H, h = idx - e * H;
    float ex = __expf(g_ev[idx] - g_segmax[g_dst[e] * H + h]);
    g_ev[idx] = ex;
    atomicAdd(&g_segsum[g_dst[e] * H + h], ex);
}

__global__ void k_edge_alpha(int H, float* __restrict__ aout) {
    int idx = blockIdx.x * blockDim.x + threadIdx.x;
    if (idx >= ET * H) return;
    int e = idx / H, h = idx - e * H;
    float a = g_ev[idx] / (g_segsum[g_dst[e] * H + h] + 1e-16f);
    g_ev[idx] = a;
    if (aout) aout[idx] = a;
}

// ---------------- CSR aggregation: one block per destination node ----------
__global__ void k_aggregate(const float* __restrict__ h, float* __restrict__ out,
                            int F, int H) {
    int n = blockIdx.x;
    float acc[5];
    #pragma unroll
    for (int j = 0; j < 5; j++) acc[j] = 0.f;
    int start = g_rowptr[n], end = g_rowptr[n + 1];
    for (int i = start; i < end; i++) {
        int eid = g_eid[i];
        int s = g_src[eid];
        const float* hs = h + (size_t)s * F;
        const float* al = g_ev + (size_t)eid * H;
        int j = 0;
        for (int c = threadIdx.x; c < F; c += blockDim.x, j++)
            acc[j] += __ldg(hs + c) * __ldg(al + (c >> 7));   // head = c / 128
    }
    int j = 0;
    for (int c = threadIdx.x; c < F; c += blockDim.x, j++)
        out[(size_t)n * F + c] = acc[j];
}

// ---------------- elementwise ----------------
__global__ void k_elu_bias(float* __restrict__ x, const float* __restrict__ b,
                           int F, int total) {
    int i = blockIdx.x * blockDim.x + threadIdx.x;
    if (i >= total) return;
    float v = x[i] + b[i % F];
    x[i] = (v > 0.f) ? v : expm1f(v);
}

__global__ void k_fill(float* __restrict__ p, float v, int n) {
    int i = blockIdx.x * blockDim.x + threadIdx.x;
    if (i < n) p[i] = v;
}

__global__ void k_pool(const float* __restrict__ h2a,
                       const int* __restrict__ batch,
                       float* __restrict__ out) {
    int i = blockIdx.x * blockDim.x + threadIdx.x;
    if (i >= NN * CC) return;
    int n = i >> 7, c = i & 127;
    int g = batch[n];
    atomicMaxF(&out[g * CC + c], h2a[i]);
}

// ---------------- launch ----------------
extern "C" void kernel_launch(void* const* d_in, const int* in_sizes, int n_in,
                              void* d_out, int out_size) {
    const float* x     = (const float*)d_in[0];
    const int*   ei    = (const int*)d_in[1];     // int32 (JAX x64 disabled)
    const int*   batch = (const int*)d_in[2];     // int32
    const float* W1    = (const float*)d_in[3];
    const float* as1   = (const float*)d_in[4];
    const float* ad1   = (const float*)d_in[5];
    const float* b1    = (const float*)d_in[6];
    const float* W2    = (const float*)d_in[7];
    const float* as2   = (const float*)d_in[8];
    const float* ad2   = (const float*)d_in[9];
    const float* b2    = (const float*)d_in[10];

    float* out       = (float*)d_out;
    float* pooled    = out;              // [64, 128]
    float* alpha_out = out + GG * CC;    // [170000, 10]

    float *p_h1, *p_out1, *p_h2, *p_out2, *p_asrc, *p_adst;
    cudaGetSymbolAddress((void**)&p_h1,   g_h1);
    cudaGetSymbolAddress((void**)&p_out1, g_out1);
    cudaGetSymbolAddress((void**)&p_h2,   g_h2);
    cudaGetSymbolAddress((void**)&p_out2, g_out2);
    cudaGetSymbolAddress((void**)&p_asrc, g_asrc);
    cudaGetSymbolAddress((void**)&p_adst, g_adst);

    // CSR build (shared by both layers)
    k_prep_edges<<<(ET + 255) / 256, 256>>>(ei);
    k_zero_deg  <<<(NN + 255) / 256, 256>>>();
    k_count     <<<(ET + 255) / 256, 256>>>();
    k_scan      <<<1, 1024>>>();
    k_scatter   <<<(ET + 255) / 256, 256>>>();

    // ---- layer 1 (H=10) ----
    k_gemm<<<dim3((NN + 63) / 64, (F1 + 63) / 64), 256>>>(x, W1, p_h1, NN, FIN, F1);
    k_alphadot<<<NN, HH * 32>>>(p_h1, as1, ad1, p_asrc, p_adst, HH);
    k_initseg<<<(NN * HH + 255) / 256, 256>>>(NN * HH);
    k_edge_e    <<<(ET * HH + 255) / 256, 256>>>(HH);
    k_edge_exp  <<<(ET * HH + 255) / 256, 256>>>(HH);
    k_edge_alpha<<<(ET * HH + 255) / 256, 256>>>(HH, alpha_out);
    k_aggregate<<<NN, 256>>>(p_h1, p_out1, F1, HH);
    k_elu_bias<<<(NN * F1 + 255) / 256, 256>>>(p_out1, b1, F1, NN * F1);

    // ---- layer 2 (H=1) ----
    k_gemm<<<dim3((NN + 63) / 64, (CC + 63) / 64), 256>>>(p_out1, W2, p_h2, NN, F1, CC);
    k_alphadot<<<NN, 32>>>(p_h2, as2, ad2, p_asrc, p_adst, 1);
    k_initseg<<<(NN + 255) / 256, 256>>>(NN);
    k_edge_e    <<<(ET + 255) / 256, 256>>>(1);
    k_edge_exp  <<<(ET + 255) / 256, 256>>>(1);
    k_edge_alpha<<<(ET + 255) / 256, 256>>>(1, nullptr);
    k_aggregate<<<NN, 128>>>(p_h2, p_out2, CC, 1);
    k_elu_bias<<<(NN * CC + 255) / 256, 256>>>(p_out2, b2, CC, NN * CC);

    // ---- global max pool ----
    k_fill<<<(GG * CC + 255) / 256, 256>>>(pooled, -INFINITY, GG * CC);
    k_pool<<<(NN * CC + 255) / 256, 256>>>(p_out2, batch, pooled);
}

// round 6
// speedup vs baseline: 1.5058x; 1.5058x over previous
#include <cuda_runtime.h>
#include <math.h>

#define NN   10000
#define EE   160000
#define ET   170000
#define FIN  78
#define CC   128
#define HH   10
#define F1   1280
#define GG   64

#define NEG_INF __int_as_float(0xff800000)

// ---------------- scratch (device globals; allocation-free) ----------------
__device__ __align__(16) float g_h1[(size_t)NN * F1];
__device__ __align__(16) float g_out1[(size_t)NN * F1];
__device__ __align__(16) float g_h2[(size_t)NN * CC];
__device__ __align__(16) float g_out2[(size_t)NN * CC];
__device__ float g_asrc[NN * HH];
__device__ float g_adst[NN * HH];
__device__ float g_segmax[NN * HH];
__device__ float g_segsum[NN * HH];
__device__ float g_ev[(size_t)ET * HH];
__device__ int   g_src[ET];
__device__ int   g_dst[ET];
__device__ int   g_deg[NN];
__device__ int   g_rowptr[NN + 1];
__device__ int   g_cursor[NN];
__device__ int   g_eid[ET];

__device__ __forceinline__ void atomicMaxF(float* addr, float v) {
    if (v >= 0.f) atomicMax((int*)addr, __float_as_int(v));
    else          atomicMin((unsigned int*)addr, __float_as_uint(v));
}

// ---------------- edge prep (+ zero deg) ----------------
__global__ void k_prep_edges(const int* __restrict__ ei) {
    int i = blockIdx.x * blockDim.x + threadIdx.x;
    if (i < NN) g_deg[i] = 0;
    if (i >= ET) return;
    int s, d;
    if (i < EE) { s = ei[i]; d = ei[EE + i]; }
    else        { s = d = i - EE; }
    g_src[i] = s;
    g_dst[i] = d;
}

__global__ void k_count() {
    int i = blockIdx.x * blockDim.x + threadIdx.x;
    if (i < ET) atomicAdd(&g_deg[g_dst[i]], 1);
}

// warp-shuffle scan, 1024 threads
__global__ void k_scan() {
    __shared__ int wsum[32];
    __shared__ int carry;
    int tid = threadIdx.x, lane = tid & 31, wid = tid >> 5;
    if (tid == 0) carry = 0;
    __syncthreads();
    for (int base = 0; base < NN; base += 1024) {
        int i = base + tid;
        int v = (i < NN) ? g_deg[i] : 0;
        int x = v;
        #pragma unroll
        for (int o = 1; o < 32; o <<= 1) {
            int t = __shfl_up_sync(0xffffffff, x, o);
            if (lane >= o) x += t;
        }
        if (lane == 31) wsum[wid] = x;
        __syncthreads();
        if (wid == 0) {
            int s = wsum[lane];
            #pragma unroll
            for (int o = 1; o < 32; o <<= 1) {
                int t = __shfl_up_sync(0xffffffff, s, o);
                if (lane >= o) s += t;
            }
            wsum[lane] = s;
        }
        __syncthreads();
        int excl = carry + (wid ? wsum[wid - 1] : 0) + x - v;
        if (i < NN) { g_rowptr[i] = excl; g_cursor[i] = excl; }
        __syncthreads();
        if (tid == 0) carry += wsum[31];
        __syncthreads();
    }
    if (threadIdx.x == 0) g_rowptr[NN] = carry;
}

__global__ void k_scatter() {
    int i = blockIdx.x * blockDim.x + threadIdx.x;
    if (i >= ET) return;
    int pos = atomicAdd(&g_cursor[g_dst[i]], 1);
    g_eid[pos] = i;
}

// ---------------- GEMM: 64x128 tile, BK=16, 256 thr, 4x8/thread ------------
__global__ void __launch_bounds__(256) k_gemm(const float* __restrict__ A,
                                              const float* __restrict__ B,
                                              float* __restrict__ Cm,
                                              int M, int K, int Nn) {
    const int BM = 64, BN = 128, BK = 16;
    __shared__ float As[BK][BM];
    __shared__ float Bs[BK][BN];
    int tid = threadIdx.x;
    int tx = tid & 15, ty = tid >> 4;       // tx: 8-col group, ty: 4-row group
    int bm0 = blockIdx.x * BM, bn0 = blockIdx.y * BN;
    float acc[4][8];
    #pragma unroll
    for (int i = 0; i < 4; i++)
        #pragma unroll
        for (int j = 0; j < 8; j++) acc[i][j] = 0.f;

    for (int k0 = 0; k0 < K; k0 += BK) {
        #pragma unroll
        for (int i = 0; i < 4; i++) {
            int t = tid + i * 256;
            int m = t >> 4, k = t & 15;
            int gr = bm0 + m, gk = k0 + k;
            As[k][m] = (gr < M && gk < K) ? A[(size_t)gr * K + gk] : 0.f;
        }
        #pragma unroll
        for (int i = 0; i < 8; i++) {
            int t = tid + i * 256;
            int k = t >> 7, n = t & 127;
            int gk = k0 + k;
            Bs[k][n] = (gk < K) ? B[(size_t)gk * Nn + bn0 + n] : 0.f;
        }
        __syncthreads();
        #pragma unroll
        for (int k = 0; k < BK; k++) {
            float4 a4 = *(const float4*)&As[k][ty * 4];
            float4 b0 = *(const float4*)&Bs[k][tx * 8];
            float4 b1 = *(const float4*)&Bs[k][tx * 8 + 4];
            float a[4] = {a4.x, a4.y, a4.z, a4.w};
            float b[8] = {b0.x, b0.y, b0.z, b0.w, b1.x, b1.y, b1.z, b1.w};
            #pragma unroll
            for (int i = 0; i < 4; i++)
                #pragma unroll
                for (int j = 0; j < 8; j++) acc[i][j] += a[i] * b[j];
        }
        __syncthreads();
    }
    #pragma unroll
    for (int i = 0; i < 4; i++) {
        int gr = bm0 + ty * 4 + i;
        if (gr >= M) continue;
        float4 c0 = {acc[i][0], acc[i][1], acc[i][2], acc[i][3]};
        float4 c1 = {acc[i][4], acc[i][5], acc[i][6], acc[i][7]};
        float* cp = Cm + (size_t)gr * Nn + bn0 + tx * 8;
        *(float4*)cp = c0;
        *(float4*)(cp + 4) = c1;
    }
}

// ---------------- attention dots (+ segment init) ----------------
__global__ void k_alphadot(const float* __restrict__ h,
                           const float* __restrict__ wsrc,
                           const float* __restrict__ wdst,
                           float* __restrict__ asrc, float* __restrict__ adst,
                           int H) {
    int n = blockIdx.x;
    int wid = threadIdx.x >> 5, lane = threadIdx.x & 31;
    if (wid >= H) return;
    const float* hr = h + ((size_t)n * H + wid) * CC;
    const float* ws = wsrc + wid * CC;
    const float* wd = wdst + wid * CC;
    float s1 = 0.f, s2 = 0.f;
    #pragma unroll
    for (int c = lane; c < CC; c += 32) {
        float v = hr[c];
        s1 += v * ws[c];
        s2 += v * wd[c];
    }
    #pragma unroll
    for (int o = 16; o > 0; o >>= 1) {
        s1 += __shfl_down_sync(0xffffffff, s1, o);
        s2 += __shfl_down_sync(0xffffffff, s2, o);
    }
    if (lane == 0) {
        asrc[n * H + wid] = s1;
        adst[n * H + wid] = s2;
        g_segmax[n * H + wid] = NEG_INF;
        g_segsum[n * H + wid] = 0.f;
    }
}

// ---------------- edge softmax ----------------
__global__ void k_edge_e(int H) {
    int idx = blockIdx.x * blockDim.x + threadIdx.x;
    if (idx >= ET * H) return;
    int e = idx / H, h = idx - e * H;
    float v = g_asrc[g_src[e] * H + h] + g_adst[g_dst[e] * H + h];
    v = (v >= 0.f) ? v : 0.2f * v;
    g_ev[idx] = v;
    atomicMaxF(&g_segmax[g_dst[e] * H + h], v);
}

__global__ void k_edge_exp(int H) {
    int idx = blockIdx.x * blockDim.x + threadIdx.x;
    if (idx >= ET * H) return;
    int e = idx / H, h = idx - e * H;
    float ex = __expf(g_ev[idx] - g_segmax[g_dst[e] * H + h]);
    g_ev[idx] = ex;
    atomicAdd(&g_segsum[g_dst[e] * H + h], ex);
}

__global__ void k_edge_alpha(int H, float* __restrict__ aout) {
    int idx = blockIdx.x * blockDim.x + threadIdx.x;
    if (idx >= ET * H) return;
    int e = idx / H, h = idx - e * H;
    float a = g_ev[idx] / (g_segsum[g_dst[e] * H + h] + 1e-16f);
    g_ev[idx] = a;
    if (aout) aout[idx] = a;
}

// ------------- layer-1 aggregate (320 thr, float4) + bias + elu -------------
__global__ void __launch_bounds__(320) k_agg1(const float* __restrict__ h,
                                              const float* __restrict__ bias,
                                              float* __restrict__ out) {
    int n = blockIdx.x;
    int tid = threadIdx.x;             // 0..319, covers 1280 floats as float4
    int head = tid >> 5;               // 32 float4 = 128 floats per head
    float4 acc = {0.f, 0.f, 0.f, 0.f};
    int start = g_rowptr[n], end = g_rowptr[n + 1];
    const float4* h4 = (const float4*)h;
    for (int i = start; i < end; i++) {
        int eid = g_eid[i];
        int s = g_src[eid];
        float al = __ldg(&g_ev[(size_t)eid * HH + head]);
        float4 v = __ldg(&h4[(size_t)s * (F1 / 4) + tid]);
        acc.x += v.x * al; acc.y += v.y * al;
        acc.z += v.z * al; acc.w += v.w * al;
    }
    float4 bb = __ldg(&((const float4*)bias)[tid]);
    acc.x += bb.x; acc.y += bb.y; acc.z += bb.z; acc.w += bb.w;
    acc.x = (acc.x > 0.f) ? acc.x : expm1f(acc.x);
    acc.y = (acc.y > 0.f) ? acc.y : expm1f(acc.y);
    acc.z = (acc.z > 0.f) ? acc.z : expm1f(acc.z);
    acc.w = (acc.w > 0.f) ? acc.w : expm1f(acc.w);
    ((float4*)out)[(size_t)n * (F1 / 4) + tid] = acc;
}

// ------------- layer-2 aggregate (32 thr, float4) + bias + elu + pool init --
__global__ void k_agg2(const float* __restrict__ h,
                       const float* __restrict__ bias,
                       float* __restrict__ out,
                       float* __restrict__ pooled) {
    int n = blockIdx.x;
    int tid = threadIdx.x;             // 0..31, covers 128 floats as float4
    if (n < (GG * CC) / 32) pooled[n * 32 + tid] = NEG_INF;
    float4 acc = {0.f, 0.f, 0.f, 0.f};
    int start = g_rowptr[n], end = g_rowptr[n + 1];
    const float4* h4 = (const float4*)h;
    for (int i = start; i < end; i++) {
        int eid = g_eid[i];
        int s = g_src[eid];
        float al = __ldg(&g_ev[eid]);
        float4 v = __ldg(&h4[(size_t)s * (CC / 4) + tid]);
        acc.x += v.x * al; acc.y += v.y * al;
        acc.z += v.z * al; acc.w += v.w * al;
    }
    float4 bb = __ldg(&((const float4*)bias)[tid]);
    acc.x += bb.x; acc.y += bb.y; acc.z += bb.z; acc.w += bb.w;
    acc.x = (acc.x > 0.f) ? acc.x : expm1f(acc.x);
    acc.y = (acc.y > 0.f) ? acc.y : expm1f(acc.y);
    acc.z = (acc.z > 0.f) ? acc.z : expm1f(acc.z);
    acc.w = (acc.w > 0.f) ? acc.w : expm1f(acc.w);
    ((float4*)out)[(size_t)n * (CC / 4) + tid] = acc;
}

__global__ void k_pool(const float* __restrict__ h2a,
                       const int* __restrict__ batch,
                       float* __restrict__ out) {
    int i = blockIdx.x * blockDim.x + threadIdx.x;
    if (i >= NN * CC) return;
    int n = i >> 7, c = i & 127;
    int g = batch[n];
    atomicMaxF(&out[g * CC + c], h2a[i]);
}

// ---------------- launch ----------------
extern "C" void kernel_launch(void* const* d_in, const int* in_sizes, int n_in,
                              void* d_out, int out_size) {
    const float* x     = (const float*)d_in[0];
    const int*   ei    = (const int*)d_in[1];
    const int*   batch = (const int*)d_in[2];
    const float* W1    = (const float*)d_in[3];
    const float* as1   = (const float*)d_in[4];
    const float* ad1   = (const float*)d_in[5];
    const float* b1    = (const float*)d_in[6];
    const float* W2    = (const float*)d_in[7];
    const float* as2   = (const float*)d_in[8];
    const float* ad2   = (const float*)d_in[9];
    const float* b2    = (const float*)d_in[10];

    float* out       = (float*)d_out;
    float* pooled    = out;              // [64, 128]
    float* alpha_out = out + GG * CC;    // [170000, 10]

    float *p_h1, *p_out1, *p_h2, *p_out2, *p_asrc, *p_adst;
    cudaGetSymbolAddress((void**)&p_h1,   g_h1);
    cudaGetSymbolAddress((void**)&p_out1, g_out1);
    cudaGetSymbolAddress((void**)&p_h2,   g_h2);
    cudaGetSymbolAddress((void**)&p_out2, g_out2);
    cudaGetSymbolAddress((void**)&p_asrc, g_asrc);
    cudaGetSymbolAddress((void**)&p_adst, g_adst);

    // CSR build
    k_prep_edges<<<(ET + 255) / 256, 256>>>(ei);
    k_count     <<<(ET + 255) / 256, 256>>>();
    k_scan      <<<1, 1024>>>();
    k_scatter   <<<(ET + 255) / 256, 256>>>();

    // ---- layer 1 (H=10) ----
    k_gemm<<<dim3((NN + 63) / 64, F1 / 128), 256>>>(x, W1, p_h1, NN, FIN, F1);
    k_alphadot<<<NN, HH * 32>>>(p_h1, as1, ad1, p_asrc, p_adst, HH);
    k_edge_e    <<<(ET * HH + 255) / 256, 256>>>(HH);
    k_edge_exp  <<<(ET * HH + 255) / 256, 256>>>(HH);
    k_edge_alpha<<<(ET * HH + 255) / 256, 256>>>(HH, alpha_out);
    k_agg1<<<NN, 320>>>(p_h1, b1, p_out1);

    // ---- layer 2 (H=1) ----
    k_gemm<<<dim3((NN + 63) / 64, CC / 128), 256>>>(p_out1, W2, p_h2, NN, F1, CC);
    k_alphadot<<<NN, 32>>>(p_h2, as2, ad2, p_asrc, p_adst, 1);
    k_edge_e    <<<(ET + 255) / 256, 256>>>(1);
    k_edge_exp  <<<(ET + 255) / 256, 256>>>(1);
    k_edge_alpha<<<(ET + 255) / 256, 256>>>(1, nullptr);
    k_agg2<<<NN, 32>>>(p_h2, b2, p_out2, pooled);

    // ---- global max pool ----
    k_pool<<<(NN * CC + 255) / 256, 256>>>(p_out2, batch, pooled);
}

// round 7
// speedup vs baseline: 2.3207x; 1.5412x over previous
#include <cuda_runtime.h>
#include <math.h>

#define NN   10000
#define EE   160000
#define ET   170000
#define FIN  78
#define CC   128
#define HH   10
#define F1   1280
#define GG   64

#define NEG_INF __int_as_float(0xff800000)

// ---------------- scratch ----------------
__device__ __align__(16) float g_h1[(size_t)NN * F1];
__device__ __align__(16) float g_out1[(size_t)NN * F1];
__device__ __align__(16) float g_h2[(size_t)NN * CC];
__device__ __align__(16) float g_h2p[(size_t)4 * NN * CC];   // split-K partials
__device__ __align__(16) float g_out2[(size_t)NN * CC];
__device__ float g_asrc[NN * HH];
__device__ float g_adst[NN * HH];
__device__ float g_segmax[NN * HH];
__device__ float g_segsum[NN * HH];
__device__ float g_ev[(size_t)ET * HH];
__device__ int   g_src[ET];
__device__ int   g_dst[ET];
__device__ int   g_deg[NN];
__device__ int   g_rowptr[NN + 1];
__device__ int   g_cursor[NN];
__device__ int   g_eid[ET];

__device__ __forceinline__ void atomicMaxF(float* addr, float v) {
    if (v >= 0.f) atomicMax((int*)addr, __float_as_int(v));
    else          atomicMin((unsigned int*)addr, __float_as_uint(v));
}

// ---------------- CSR build ----------------
__global__ void k_zero_deg() {
    int i = blockIdx.x * blockDim.x + threadIdx.x;
    if (i < NN) g_deg[i] = 0;
}

__global__ void k_prep_count(const int* __restrict__ ei) {
    int i = blockIdx.x * blockDim.x + threadIdx.x;
    if (i >= ET) return;
    int s, d;
    if (i < EE) { s = ei[i]; d = ei[EE + i]; }
    else        { s = d = i - EE; }
    g_src[i] = s;
    g_dst[i] = d;
    atomicAdd(&g_deg[d], 1);
}

__global__ void k_scan() {   // 1024 threads, warp-shuffle scan
    __shared__ int wsum[32];
    __shared__ int carry;
    int tid = threadIdx.x, lane = tid & 31, wid = tid >> 5;
    if (tid == 0) carry = 0;
    __syncthreads();
    for (int base = 0; base < NN; base += 1024) {
        int i = base + tid;
        int v = (i < NN) ? g_deg[i] : 0;
        int x = v;
        #pragma unroll
        for (int o = 1; o < 32; o <<= 1) {
            int t = __shfl_up_sync(0xffffffff, x, o);
            if (lane >= o) x += t;
        }
        if (lane == 31) wsum[wid] = x;
        __syncthreads();
        if (wid == 0) {
            int s = wsum[lane];
            #pragma unroll
            for (int o = 1; o < 32; o <<= 1) {
                int t = __shfl_up_sync(0xffffffff, s, o);
                if (lane >= o) s += t;
            }
            wsum[lane] = s;
        }
        __syncthreads();
        int excl = carry + (wid ? wsum[wid - 1] : 0) + x - v;
        if (i < NN) { g_rowptr[i] = excl; g_cursor[i] = excl; }
        __syncthreads();
        if (tid == 0) carry += wsum[31];
        __syncthreads();
    }
    if (threadIdx.x == 0) g_rowptr[NN] = carry;
}

__global__ void k_scatter() {
    int i = blockIdx.x * blockDim.x + threadIdx.x;
    if (i >= ET) return;
    int pos = atomicAdd(&g_cursor[g_dst[i]], 1);
    g_eid[pos] = i;
}

// ------- GEMM1: x@W1 (128x128 tile, 8x8/thr) + fused attention dots --------
__global__ void __launch_bounds__(256) k_gemm1(const float* __restrict__ A,
                                               const float* __restrict__ B,
                                               float* __restrict__ C,
                                               const float* __restrict__ wsrc,
                                               const float* __restrict__ wdst) {
    const int M = NN, K = FIN, Nn = F1;
    __shared__ float As[16][132];
    __shared__ float Bs[16][128];
    int tid = threadIdx.x;
    int tx = tid & 15, ty = tid >> 4;
    int bm0 = blockIdx.x * 128;
    int head = blockIdx.y;
    int bn0 = head * 128;
    float acc[8][8];
    #pragma unroll
    for (int i = 0; i < 8; i++)
        #pragma unroll
        for (int j = 0; j < 8; j++) acc[i][j] = 0.f;

    for (int k0 = 0; k0 < K; k0 += 16) {
        int kk = tid & 15, r0 = tid >> 4;
        int gk = k0 + kk;
        bool kok = gk < K;
        #pragma unroll
        for (int u = 0; u < 8; u++) {
            int r = r0 + u * 16;
            int gr = bm0 + r;
            As[kk][r] = (kok && gr < M) ? A[(size_t)gr * K + gk] : 0.f;
        }
        #pragma unroll
        for (int p = 0; p < 2; p++) {
            int f = tid + p * 256;
            int k = f >> 5, n = (f & 31) * 4;
            int gk2 = k0 + k;
            float4 v = make_float4(0.f, 0.f, 0.f, 0.f);
            if (gk2 < K) v = *(const float4*)&B[(size_t)gk2 * Nn + bn0 + n];
            *(float4*)&Bs[k][n] = v;
        }
        __syncthreads();
        #pragma unroll
        for (int k = 0; k < 16; k++) {
            float a[8], b[8];
            *(float4*)&a[0] = *(const float4*)&As[k][ty * 8];
            *(float4*)&a[4] = *(const float4*)&As[k][ty * 8 + 4];
            *(float4*)&b[0] = *(const float4*)&Bs[k][tx * 8];
            *(float4*)&b[4] = *(const float4*)&Bs[k][tx * 8 + 4];
            #pragma unroll
            for (int i = 0; i < 8; i++)
                #pragma unroll
                for (int j = 0; j < 8; j++) acc[i][j] += a[i] * b[j];
        }
        __syncthreads();
    }
    // epilogue: store h1 + complete per-head attention dots (block col == head)
    float ws[8], wd[8];
    #pragma unroll
    for (int j = 0; j < 8; j++) {
        ws[j] = wsrc[head * CC + tx * 8 + j];
        wd[j] = wdst[head * CC + tx * 8 + j];
    }
    #pragma unroll
    for (int i = 0; i < 8; i++) {
        int gr = bm0 + ty * 8 + i;
        bool ok = gr < M;
        if (ok) {
            float4 c0 = {acc[i][0], acc[i][1], acc[i][2], acc[i][3]};
            float4 c1 = {acc[i][4], acc[i][5], acc[i][6], acc[i][7]};
            float* cp = C + (size_t)gr * Nn + bn0 + tx * 8;
            *(float4*)cp = c0;
            *(float4*)(cp + 4) = c1;
        }
        float s1 = 0.f, s2 = 0.f;
        #pragma unroll
        for (int j = 0; j < 8; j++) { s1 += acc[i][j] * ws[j]; s2 += acc[i][j] * wd[j]; }
        #pragma unroll
        for (int o = 8; o > 0; o >>= 1) {
            s1 += __shfl_down_sync(0xffffffffu, s1, o);
            s2 += __shfl_down_sync(0xffffffffu, s2, o);
        }
        if (tx == 0 && ok) {
            g_asrc[gr * HH + head] = s1;
            g_adst[gr * HH + head] = s2;
            g_segmax[gr * HH + head] = NEG_INF;
            g_segsum[gr * HH + head] = 0.f;
        }
    }
}

// ------- GEMM2: h1a@W2, split-K=4 partials ---------------------------------
__global__ void __launch_bounds__(256) k_gemm2p(const float* __restrict__ A,
                                                const float* __restrict__ B,
                                                float* __restrict__ Cp) {
    const int M = NN, K = F1, Nn = CC, KS = F1 / 4;   // 320 per z
    __shared__ float As[16][132];
    __shared__ float Bs[16][128];
    int tid = threadIdx.x;
    int tx = tid & 15, ty = tid >> 4;
    int bm0 = blockIdx.x * 128;
    int z = blockIdx.z;
    float* C = Cp + (size_t)z * M * Nn;
    float acc[8][8];
    #pragma unroll
    for (int i = 0; i < 8; i++)
        #pragma unroll
        for (int j = 0; j < 8; j++) acc[i][j] = 0.f;

    int kbeg = z * KS;
    for (int k0 = kbeg; k0 < kbeg + KS; k0 += 16) {
        int kk = tid & 15, r0 = tid >> 4;
        int gk = k0 + kk;
        #pragma unroll
        for (int u = 0; u < 8; u++) {
            int r = r0 + u * 16;
            int gr = bm0 + r;
            As[kk][r] = (gr < M) ? A[(size_t)gr * K + gk] : 0.f;
        }
        #pragma unroll
        for (int p = 0; p < 2; p++) {
            int f = tid + p * 256;
            int k = f >> 5, n = (f & 31) * 4;
            *(float4*)&Bs[k][n] = *(const float4*)&B[(size_t)(k0 + k) * Nn + n];
        }
        __syncthreads();
        #pragma unroll
        for (int k = 0; k < 16; k++) {
            float a[8], b[8];
            *(float4*)&a[0] = *(const float4*)&As[k][ty * 8];
            *(float4*)&a[4] = *(const float4*)&As[k][ty * 8 + 4];
            *(float4*)&b[0] = *(const float4*)&Bs[k][tx * 8];
            *(float4*)&b[4] = *(const float4*)&Bs[k][tx * 8 + 4];
            #pragma unroll
            for (int i = 0; i < 8; i++)
                #pragma unroll
                for (int j = 0; j < 8; j++) acc[i][j] += a[i] * b[j];
        }
        __syncthreads();
    }
    #pragma unroll
    for (int i = 0; i < 8; i++) {
        int gr = bm0 + ty * 8 + i;
        if (gr >= M) continue;
        float4 c0 = {acc[i][0], acc[i][1], acc[i][2], acc[i][3]};
        float4 c1 = {acc[i][4], acc[i][5], acc[i][6], acc[i][7]};
        float* cp = C + (size_t)gr * Nn + tx * 8;
        *(float4*)cp = c0;
        *(float4*)(cp + 4) = c1;
    }
}

// ------- finish layer-2 pre-agg: sum partials + dots + seg init -------------
__global__ void k_finish2(float* __restrict__ h2,
                          const float* __restrict__ ws,
                          const float* __restrict__ wd) {
    int n = blockIdx.x * 8 + (threadIdx.x >> 5);
    int lane = threadIdx.x & 31;
    if (n >= NN) return;
    const float4* p4 = (const float4*)g_h2p;
    float4 v = p4[(size_t)n * 32 + lane];
    #pragma unroll
    for (int z = 1; z < 4; z++) {
        float4 t = p4[(size_t)z * NN * 32 + (size_t)n * 32 + lane];
        v.x += t.x; v.y += t.y; v.z += t.z; v.w += t.w;
    }
    ((float4*)h2)[(size_t)n * 32 + lane] = v;
    float4 w1 = ((const float4*)ws)[lane];
    float4 w2 = ((const float4*)wd)[lane];
    float s1 = v.x * w1.x + v.y * w1.y + v.z * w1.z + v.w * w1.w;
    float s2 = v.x * w2.x + v.y * w2.y + v.z * w2.z + v.w * w2.w;
    #pragma unroll
    for (int o = 16; o > 0; o >>= 1) {
        s1 += __shfl_down_sync(0xffffffffu, s1, o);
        s2 += __shfl_down_sync(0xffffffffu, s2, o);
    }
    if (lane == 0) {
        g_asrc[n] = s1;
        g_adst[n] = s2;
        g_segmax[n] = NEG_INF;
        g_segsum[n] = 0.f;
    }
}

// ---------------- edge softmax ----------------
__global__ void k_edge_e(int H) {
    int idx = blockIdx.x * blockDim.x + threadIdx.x;
    if (idx >= ET * H) return;
    int e = idx / H, h = idx - e * H;
    float v = g_asrc[g_src[e] * H + h] + g_adst[g_dst[e] * H + h];
    v = (v >= 0.f) ? v : 0.2f * v;
    g_ev[idx] = v;
    atomicMaxF(&g_segmax[g_dst[e] * H + h], v);
}

__global__ void k_edge_exp(int H) {
    int idx = blockIdx.x * blockDim.x + threadIdx.x;
    if (idx >= ET * H) return;
    int e = idx / H, h = idx - e * H;
    float ex = __expf(g_ev[idx] - g_segmax[g_dst[e] * H + h]);
    g_ev[idx] = ex;
    atomicAdd(&g_segsum[g_dst[e] * H + h], ex);
}

__global__ void k_edge_alpha(int H, float* __restrict__ aout) {
    int idx = blockIdx.x * blockDim.x + threadIdx.x;
    if (idx >= ET * H) return;
    int e = idx / H, h = idx - e * H;
    float a = __fdividef(g_ev[idx], g_segsum[g_dst[e] * H + h] + 1e-16f);
    g_ev[idx] = a;
    if (aout) aout[idx] = a;
}

// ------------- layer-1 aggregate + bias + elu -------------
__global__ void __launch_bounds__(320) k_agg1(const float* __restrict__ h,
                                              const float* __restrict__ bias,
                                              float* __restrict__ out) {
    int n = blockIdx.x;
    int tid = threadIdx.x;
    int head = tid >> 5;
    float4 acc = {0.f, 0.f, 0.f, 0.f};
    int start = g_rowptr[n], end = g_rowptr[n + 1];
    const float4* h4 = (const float4*)h;
    for (int i = start; i < end; i++) {
        int eid = g_eid[i];
        int s = g_src[eid];
        float al = __ldg(&g_ev[(size_t)eid * HH + head]);
        float4 v = __ldg(&h4[(size_t)s * (F1 / 4) + tid]);
        acc.x += v.x * al; acc.y += v.y * al;
        acc.z += v.z * al; acc.w += v.w * al;
    }
    float4 bb = __ldg(&((const float4*)bias)[tid]);
    acc.x += bb.x; acc.y += bb.y; acc.z += bb.z; acc.w += bb.w;
    acc.x = (acc.x > 0.f) ? acc.x : expm1f(acc.x);
    acc.y = (acc.y > 0.f) ? acc.y : expm1f(acc.y);
    acc.z = (acc.z > 0.f) ? acc.z : expm1f(acc.z);
    acc.w = (acc.w > 0.f) ? acc.w : expm1f(acc.w);
    ((float4*)out)[(size_t)n * (F1 / 4) + tid] = acc;
}

// ------------- layer-2 aggregate + bias + elu + pool init -------------
__global__ void k_agg2(const float* __restrict__ h,
                       const float* __restrict__ bias,
                       float* __restrict__ out,
                       float* __restrict__ pooled) {
    int n = blockIdx.x;
    int tid = threadIdx.x;
    if (n < (GG * CC) / 32) pooled[n * 32 + tid] = NEG_INF;
    float4 acc = {0.f, 0.f, 0.f, 0.f};
    int start = g_rowptr[n], end = g_rowptr[n + 1];
    const float4* h4 = (const float4*)h;
    for (int i = start; i < end; i++) {
        int eid = g_eid[i];
        int s = g_src[eid];
        float al = __ldg(&g_ev[eid]);
        float4 v = __ldg(&h4[(size_t)s * (CC / 4) + tid]);
        acc.x += v.x * al; acc.y += v.y * al;
        acc.z += v.z * al; acc.w += v.w * al;
    }
    float4 bb = __ldg(&((const float4*)bias)[tid]);
    acc.x += bb.x; acc.y += bb.y; acc.z += bb.z; acc.w += bb.w;
    acc.x = (acc.x > 0.f) ? acc.x : expm1f(acc.x);
    acc.y = (acc.y > 0.f) ? acc.y : expm1f(acc.y);
    acc.z = (acc.z > 0.f) ? acc.z : expm1f(acc.z);
    acc.w = (acc.w > 0.f) ? acc.w : expm1f(acc.w);
    ((float4*)out)[(size_t)n * (CC / 4) + tid] = acc;
}

__global__ void k_pool(const float* __restrict__ h2a,
                       const int* __restrict__ batch,
                       float* __restrict__ out) {
    int i = blockIdx.x * blockDim.x + threadIdx.x;
    if (i >= NN * CC) return;
    int n = i >> 7, c = i & 127;
    int g = batch[n];
    atomicMaxF(&out[g * CC + c], h2a[i]);
}

// ---------------- launch ----------------
extern "C" void kernel_launch(void* const* d_in, const int* in_sizes, int n_in,
                              void* d_out, int out_size) {
    const float* x     = (const float*)d_in[0];
    const int*   ei    = (const int*)d_in[1];
    const int*   batch = (const int*)d_in[2];
    const float* W1    = (const float*)d_in[3];
    const float* as1   = (const float*)d_in[4];
    const float* ad1   = (const float*)d_in[5];
    const float* b1    = (const float*)d_in[6];
    const float* W2    = (const float*)d_in[7];
    const float* as2   = (const float*)d_in[8];
    const float* ad2   = (const float*)d_in[9];
    const float* b2    = (const float*)d_in[10];

    float* out       = (float*)d_out;
    float* pooled    = out;              // [64, 128]
    float* alpha_out = out + GG * CC;    // [170000, 10]

    float *p_h1, *p_out1, *p_h2, *p_h2p, *p_out2;
    cudaGetSymbolAddress((void**)&p_h1,   g_h1);
    cudaGetSymbolAddress((void**)&p_out1, g_out1);
    cudaGetSymbolAddress((void**)&p_h2,   g_h2);
    cudaGetSymbolAddress((void**)&p_h2p,  g_h2p);
    cudaGetSymbolAddress((void**)&p_out2, g_out2);

    // CSR build
    k_zero_deg  <<<(NN + 255) / 256, 256>>>();
    k_prep_count<<<(ET + 255) / 256, 256>>>(ei);
    k_scan      <<<1, 1024>>>();
    k_scatter   <<<(ET + 255) / 256, 256>>>();

    // ---- layer 1 (H=10) ----
    k_gemm1<<<dim3((NN + 127) / 128, HH), 256>>>(x, W1, p_h1, as1, ad1);
    k_edge_e    <<<(ET * HH + 255) / 256, 256>>>(HH);
    k_edge_exp  <<<(ET * HH + 255) / 256, 256>>>(HH);
    k_edge_alpha<<<(ET * HH + 255) / 256, 256>>>(HH, alpha_out);
    k_agg1<<<NN, 320>>>(p_h1, b1, p_out1);

    // ---- layer 2 (H=1) ----
    k_gemm2p<<<dim3((NN + 127) / 128, 1, 4), 256>>>(p_out1, W2, p_h2p);
    k_finish2<<<(NN + 7) / 8, 256>>>(p_h2, as2, ad2);
    k_edge_e    <<<(ET + 255) / 256, 256>>>(1);
    k_edge_exp  <<<(ET + 255) / 256, 256>>>(1);
    k_edge_alpha<<<(ET + 255) / 256, 256>>>(1, nullptr);
    k_agg2<<<NN, 32>>>(p_h2, b2, p_out2, pooled);

    // ---- global max pool ----
    k_pool<<<(NN * CC + 255) / 256, 256>>>(p_out2, batch, pooled);
}

// round 8
// speedup vs baseline: 2.7501x; 1.1850x over previous
#include <cuda_runtime.h>
#include <math.h>

#define NN   10000
#define EE   160000
#define ET   170000
#define FIN  78
#define CC   128
#define HH   10
#define F1   1280
#define GG   64
#define MAXD 128

#define NEG_INF __int_as_float(0xff800000)

// ---------------- scratch ----------------
__device__ __align__(16) float g_h1[(size_t)NN * F1];
__device__ __align__(16) float g_out1[(size_t)NN * F1];
__device__ __align__(16) float g_h2[(size_t)NN * CC];
__device__ __align__(16) float g_h2p[(size_t)4 * NN * CC];
__device__ __align__(16) float g_out2[(size_t)NN * CC];
__device__ float g_asrc[NN * HH];
__device__ float g_adst[NN * HH];
__device__ int   g_src[ET];
__device__ int   g_dst[ET];
__device__ int   g_deg[NN];
__device__ int   g_rowptr[NN + 1];
__device__ int   g_cursor[NN];
__device__ int   g_eid[ET];

__device__ __forceinline__ void atomicMaxF(float* addr, float v) {
    if (v >= 0.f) atomicMax((int*)addr, __float_as_int(v));
    else          atomicMin((unsigned int*)addr, __float_as_uint(v));
}

__device__ __forceinline__ float lrelu(float v) {
    return (v >= 0.f) ? v : 0.2f * v;
}

// ---------------- CSR build ----------------
__global__ void k_zero_deg() {
    int i = blockIdx.x * blockDim.x + threadIdx.x;
    if (i < NN) g_deg[i] = 0;
}

__global__ void k_prep_count(const int* __restrict__ ei) {
    int i = blockIdx.x * blockDim.x + threadIdx.x;
    if (i >= ET) return;
    int s, d;
    if (i < EE) { s = ei[i]; d = ei[EE + i]; }
    else        { s = d = i - EE; }
    g_src[i] = s;
    g_dst[i] = d;
    atomicAdd(&g_deg[d], 1);
}

__global__ void k_scan() {
    __shared__ int wsum[32];
    __shared__ int carry;
    int tid = threadIdx.x, lane = tid & 31, wid = tid >> 5;
    if (tid == 0) carry = 0;
    __syncthreads();
    for (int base = 0; base < NN; base += 1024) {
        int i = base + tid;
        int v = (i < NN) ? g_deg[i] : 0;
        int x = v;
        #pragma unroll
        for (int o = 1; o < 32; o <<= 1) {
            int t = __shfl_up_sync(0xffffffff, x, o);
            if (lane >= o) x += t;
        }
        if (lane == 31) wsum[wid] = x;
        __syncthreads();
        if (wid == 0) {
            int s = wsum[lane];
            #pragma unroll
            for (int o = 1; o < 32; o <<= 1) {
                int t = __shfl_up_sync(0xffffffff, s, o);
                if (lane >= o) s += t;
            }
            wsum[lane] = s;
        }
        __syncthreads();
        int excl = carry + (wid ? wsum[wid - 1] : 0) + x - v;
        if (i < NN) { g_rowptr[i] = excl; g_cursor[i] = excl; }
        __syncthreads();
        if (tid == 0) carry += wsum[31];
        __syncthreads();
    }
    if (threadIdx.x == 0) g_rowptr[NN] = carry;
}

__global__ void k_scatter() {
    int i = blockIdx.x * blockDim.x + threadIdx.x;
    if (i >= ET) return;
    int pos = atomicAdd(&g_cursor[g_dst[i]], 1);
    g_eid[pos] = i;
}

// ------- GEMM1: x@W1 (128x128 tile, 8x8/thr) + fused attention dots --------
__global__ void __launch_bounds__(256) k_gemm1(const float* __restrict__ A,
                                               const float* __restrict__ B,
                                               float* __restrict__ C,
                                               const float* __restrict__ wsrc,
                                               const float* __restrict__ wdst) {
    const int M = NN, K = FIN, Nn = F1;
    __shared__ float As[16][132];
    __shared__ float Bs[16][128];
    int tid = threadIdx.x;
    int tx = tid & 15, ty = tid >> 4;
    int bm0 = blockIdx.x * 128;
    int head = blockIdx.y;
    int bn0 = head * 128;
    float acc[8][8];
    #pragma unroll
    for (int i = 0; i < 8; i++)
        #pragma unroll
        for (int j = 0; j < 8; j++) acc[i][j] = 0.f;

    for (int k0 = 0; k0 < K; k0 += 16) {
        int kk = tid & 15, r0 = tid >> 4;
        int gk = k0 + kk;
        bool kok = gk < K;
        #pragma unroll
        for (int u = 0; u < 8; u++) {
            int r = r0 + u * 16;
            int gr = bm0 + r;
            As[kk][r] = (kok && gr < M) ? A[(size_t)gr * K + gk] : 0.f;
        }
        #pragma unroll
        for (int p = 0; p < 2; p++) {
            int f = tid + p * 256;
            int k = f >> 5, n = (f & 31) * 4;
            int gk2 = k0 + k;
            float4 v = make_float4(0.f, 0.f, 0.f, 0.f);
            if (gk2 < K) v = *(const float4*)&B[(size_t)gk2 * Nn + bn0 + n];
            *(float4*)&Bs[k][n] = v;
        }
        __syncthreads();
        #pragma unroll
        for (int k = 0; k < 16; k++) {
            float a[8], b[8];
            *(float4*)&a[0] = *(const float4*)&As[k][ty * 8];
            *(float4*)&a[4] = *(const float4*)&As[k][ty * 8 + 4];
            *(float4*)&b[0] = *(const float4*)&Bs[k][tx * 8];
            *(float4*)&b[4] = *(const float4*)&Bs[k][tx * 8 + 4];
            #pragma unroll
            for (int i = 0; i < 8; i++)
                #pragma unroll
                for (int j = 0; j < 8; j++) acc[i][j] += a[i] * b[j];
        }
        __syncthreads();
    }
    float ws[8], wd[8];
    #pragma unroll
    for (int j = 0; j < 8; j++) {
        ws[j] = wsrc[head * CC + tx * 8 + j];
        wd[j] = wdst[head * CC + tx * 8 + j];
    }
    #pragma unroll
    for (int i = 0; i < 8; i++) {
        int gr = bm0 + ty * 8 + i;
        bool ok = gr < M;
        if (ok) {
            float4 c0 = {acc[i][0], acc[i][1], acc[i][2], acc[i][3]};
            float4 c1 = {acc[i][4], acc[i][5], acc[i][6], acc[i][7]};
            float* cp = C + (size_t)gr * Nn + bn0 + tx * 8;
            *(float4*)cp = c0;
            *(float4*)(cp + 4) = c1;
        }
        float s1 = 0.f, s2 = 0.f;
        #pragma unroll
        for (int j = 0; j < 8; j++) { s1 += acc[i][j] * ws[j]; s2 += acc[i][j] * wd[j]; }
        #pragma unroll
        for (int o = 8; o > 0; o >>= 1) {
            s1 += __shfl_down_sync(0xffffffffu, s1, o);
            s2 += __shfl_down_sync(0xffffffffu, s2, o);
        }
        if (tx == 0 && ok) {
            g_asrc[gr * HH + head] = s1;
            g_adst[gr * HH + head] = s2;
        }
    }
}

// ------- GEMM2: h1a@W2, split-K=4 partials ---------------------------------
__global__ void __launch_bounds__(256) k_gemm2p(const float* __restrict__ A,
                                                const float* __restrict__ B,
                                                float* __restrict__ Cp) {
    const int M = NN, K = F1, Nn = CC, KS = F1 / 4;
    __shared__ float As[16][132];
    __shared__ float Bs[16][128];
    int tid = threadIdx.x;
    int tx = tid & 15, ty = tid >> 4;
    int bm0 = blockIdx.x * 128;
    int z = blockIdx.z;
    float* C = Cp + (size_t)z * M * Nn;
    float acc[8][8];
    #pragma unroll
    for (int i = 0; i < 8; i++)
        #pragma unroll
        for (int j = 0; j < 8; j++) acc[i][j] = 0.f;

    int kbeg = z * KS;
    for (int k0 = kbeg; k0 < kbeg + KS; k0 += 16) {
        int kk = tid & 15, r0 = tid >> 4;
        int gk = k0 + kk;
        #pragma unroll
        for (int u = 0; u < 8; u++) {
            int r = r0 + u * 16;
            int gr = bm0 + r;
            As[kk][r] = (gr < M) ? A[(size_t)gr * K + gk] : 0.f;
        }
        #pragma unroll
        for (int p = 0; p < 2; p++) {
            int f = tid + p * 256;
            int k = f >> 5, n = (f & 31) * 4;
            *(float4*)&Bs[k][n] = *(const float4*)&B[(size_t)(k0 + k) * Nn + n];
        }
        __syncthreads();
        #pragma unroll
        for (int k = 0; k < 16; k++) {
            float a[8], b[8];
            *(float4*)&a[0] = *(const float4*)&As[k][ty * 8];
            *(float4*)&a[4] = *(const float4*)&As[k][ty * 8 + 4];
            *(float4*)&b[0] = *(const float4*)&Bs[k][tx * 8];
            *(float4*)&b[4] = *(const float4*)&Bs[k][tx * 8 + 4];
            #pragma unroll
            for (int i = 0; i < 8; i++)
                #pragma unroll
                for (int j = 0; j < 8; j++) acc[i][j] += a[i] * b[j];
        }
        __syncthreads();
    }
    #pragma unroll
    for (int i = 0; i < 8; i++) {
        int gr = bm0 + ty * 8 + i;
        if (gr >= M) continue;
        float4 c0 = {acc[i][0], acc[i][1], acc[i][2], acc[i][3]};
        float4 c1 = {acc[i][4], acc[i][5], acc[i][6], acc[i][7]};
        float* cp = C + (size_t)gr * Nn + tx * 8;
        *(float4*)cp = c0;
        *(float4*)(cp + 4) = c1;
    }
}

// ------- finish layer-2 pre-agg: sum partials + attention dots --------------
__global__ void k_finish2(float* __restrict__ h2,
                          const float* __restrict__ ws,
                          const float* __restrict__ wd) {
    int n = blockIdx.x * 8 + (threadIdx.x >> 5);
    int lane = threadIdx.x & 31;
    if (n >= NN) return;
    const float4* p4 = (const float4*)g_h2p;
    float4 v = p4[(size_t)n * 32 + lane];
    #pragma unroll
    for (int z = 1; z < 4; z++) {
        float4 t = p4[(size_t)z * NN * 32 + (size_t)n * 32 + lane];
        v.x += t.x; v.y += t.y; v.z += t.z; v.w += t.w;
    }
    ((float4*)h2)[(size_t)n * 32 + lane] = v;
    float4 w1 = ((const float4*)ws)[lane];
    float4 w2 = ((const float4*)wd)[lane];
    float s1 = v.x * w1.x + v.y * w1.y + v.z * w1.z + v.w * w1.w;
    float s2 = v.x * w2.x + v.y * w2.y + v.z * w2.z + v.w * w2.w;
    #pragma unroll
    for (int o = 16; o > 0; o >>= 1) {
        s1 += __shfl_down_sync(0xffffffffu, s1, o);
        s2 += __shfl_down_sync(0xffffffffu, s2, o);
    }
    if (lane == 0) { g_asrc[n] = s1; g_adst[n] = s2; }
}

// ----- layer-1: fused softmax (warp per head) + aggregate + bias + elu ------
__global__ void __launch_bounds__(320) k_agg1(const float* __restrict__ h,
                                              const float* __restrict__ bias,
                                              float* __restrict__ out,
                                              float* __restrict__ alpha_out) {
    __shared__ float s_alpha[HH][MAXD];
    __shared__ int   s_src[MAXD];
    __shared__ float s_mx[HH], s_inv[HH];
    int n = blockIdx.x;
    int tid = threadIdx.x, lane = tid & 31, w = tid >> 5;   // w = head
    int start = g_rowptr[n];
    int deg = g_rowptr[n + 1] - start;
    bool fast = (deg <= MAXD);
    float adst_h = g_adst[n * HH + w];

    // pass 1: max
    float mx = NEG_INF;
    for (int i = lane; i < deg; i += 32) {
        int eid = g_eid[start + i];
        int s = g_src[eid];
        if (w == 0 && fast) s_src[i] = s;
        float e = lrelu(g_asrc[s * HH + w] + adst_h);
        mx = fmaxf(mx, e);
    }
    #pragma unroll
    for (int o = 16; o > 0; o >>= 1) mx = fmaxf(mx, __shfl_xor_sync(0xffffffffu, mx, o));
    // pass 2: exp + sum
    float sm = 0.f;
    for (int i = lane; i < deg; i += 32) {
        int eid = g_eid[start + i];
        int s = g_src[eid];
        float e = lrelu(g_asrc[s * HH + w] + adst_h);
        float ex = __expf(e - mx);
        if (fast) s_alpha[w][i] = ex;
        sm += ex;
    }
    #pragma unroll
    for (int o = 16; o > 0; o >>= 1) sm += __shfl_xor_sync(0xffffffffu, sm, o);
    float inv = __fdividef(1.f, sm + 1e-16f);
    // pass 3: normalize, write alpha to output
    for (int i = lane; i < deg; i += 32) {
        int eid = g_eid[start + i];
        float ex;
        if (fast) ex = s_alpha[w][i];
        else {
            int s = g_src[eid];
            ex = __expf(lrelu(g_asrc[s * HH + w] + adst_h) - mx);
        }
        float a = ex * inv;
        if (fast) s_alpha[w][i] = a;
        alpha_out[(size_t)eid * HH + w] = a;
    }
    if (lane == 0) { s_mx[w] = mx; s_inv[w] = inv; }
    __syncthreads();

    // aggregate: each thread owns one float4 of the 1280-wide row
    float4 acc = {0.f, 0.f, 0.f, 0.f};
    const float4* h4 = (const float4*)h;
    if (fast) {
        for (int i = 0; i < deg; i++) {
            float al = s_alpha[w][i];
            int s = s_src[i];
            float4 v = __ldg(&h4[(size_t)s * (F1 / 4) + tid]);
            acc.x += v.x * al; acc.y += v.y * al;
            acc.z += v.z * al; acc.w += v.w * al;
        }
    } else {
        float mxw = s_mx[w], invw = s_inv[w];
        for (int i = 0; i < deg; i++) {
            int eid = g_eid[start + i];
            int s = g_src[eid];
            float al = __expf(lrelu(g_asrc[s * HH + w] + adst_h) - mxw) * invw;
            float4 v = __ldg(&h4[(size_t)s * (F1 / 4) + tid]);
            acc.x += v.x * al; acc.y += v.y * al;
            acc.z += v.z * al; acc.w += v.w * al;
        }
    }
    float4 bb = __ldg(&((const float4*)bias)[tid]);
    acc.x += bb.x; acc.y += bb.y; acc.z += bb.z; acc.w += bb.w;
    acc.x = (acc.x > 0.f) ? acc.x : expm1f(acc.x);
    acc.y = (acc.y > 0.f) ? acc.y : expm1f(acc.y);
    acc.z = (acc.z > 0.f) ? acc.z : expm1f(acc.z);
    acc.w = (acc.w > 0.f) ? acc.w : expm1f(acc.w);
    ((float4*)out)[(size_t)n * (F1 / 4) + tid] = acc;
}

// ----- layer-2: fused softmax + aggregate + bias + elu + pool init ----------
__global__ void __launch_bounds__(256) k_agg2(const float* __restrict__ h,
                                              const float* __restrict__ bias,
                                              float* __restrict__ out,
                                              float* __restrict__ pooled) {
    __shared__ float s_ex[8][MAXD];
    __shared__ int   s_src[8][MAXD];
    int gidx = blockIdx.x * 256 + threadIdx.x;
    if (gidx < GG * CC) pooled[gidx] = NEG_INF;
    int wl = threadIdx.x >> 5;
    int lane = threadIdx.x & 31;
    int n = blockIdx.x * 8 + wl;
    if (n >= NN) return;
    int start = g_rowptr[n];
    int deg = g_rowptr[n + 1] - start;
    bool fast = (deg <= MAXD);
    float adst = g_adst[n];

    float mx = NEG_INF;
    for (int i = lane; i < deg; i += 32) {
        int eid = g_eid[start + i];
        int s = g_src[eid];
        if (fast) s_src[wl][i] = s;
        float e = lrelu(g_asrc[s] + adst);
        mx = fmaxf(mx, e);
    }
    #pragma unroll
    for (int o = 16; o > 0; o >>= 1) mx = fmaxf(mx, __shfl_xor_sync(0xffffffffu, mx, o));
    float sm = 0.f;
    for (int i = lane; i < deg; i += 32) {
        int eid = g_eid[start + i];
        int s = g_src[eid];
        float ex = __expf(lrelu(g_asrc[s] + adst) - mx);
        if (fast) s_ex[wl][i] = ex;
        sm += ex;
    }
    #pragma unroll
    for (int o = 16; o > 0; o >>= 1) sm += __shfl_xor_sync(0xffffffffu, sm, o);
    float inv = __fdividef(1.f, sm + 1e-16f);

    float4 acc = {0.f, 0.f, 0.f, 0.f};
    const float4* h4 = (const float4*)h;
    if (fast) {
        for (int i = 0; i < deg; i++) {
            float al = s_ex[wl][i] * inv;
            int s = s_src[wl][i];
            float4 v = __ldg(&h4[(size_t)s * 32 + lane]);
            acc.x += v.x * al; acc.y += v.y * al;
            acc.z += v.z * al; acc.w += v.w * al;
        }
    } else {
        for (int i = 0; i < deg; i++) {
            int eid = g_eid[start + i];
            int s = g_src[eid];
            float al = __expf(lrelu(g_asrc[s] + adst) - mx) * inv;
            float4 v = __ldg(&h4[(size_t)s * 32 + lane]);
            acc.x += v.x * al; acc.y += v.y * al;
            acc.z += v.z * al; acc.w += v.w * al;
        }
    }
    float4 bb = __ldg(&((const float4*)bias)[lane]);
    acc.x += bb.x; acc.y += bb.y; acc.z += bb.z; acc.w += bb.w;
    acc.x = (acc.x > 0.f) ? acc.x : expm1f(acc.x);
    acc.y = (acc.y > 0.f) ? acc.y : expm1f(acc.y);
    acc.z = (acc.z > 0.f) ? acc.z : expm1f(acc.z);
    acc.w = (acc.w > 0.f) ? acc.w : expm1f(acc.w);
    ((float4*)out)[(size_t)n * 32 + lane] = acc;
}

__global__ void k_pool(const float* __restrict__ h2a,
                       const int* __restrict__ batch,
                       float* __restrict__ out) {
    int i = blockIdx.x * blockDim.x + threadIdx.x;
    if (i >= NN * CC) return;
    int n = i >> 7, c = i & 127;
    int g = batch[n];
    atomicMaxF(&out[g * CC + c], h2a[i]);
}

// ---------------- launch ----------------
extern "C" void kernel_launch(void* const* d_in, const int* in_sizes, int n_in,
                              void* d_out, int out_size) {
    const float* x     = (const float*)d_in[0];
    const int*   ei    = (const int*)d_in[1];
    const int*   batch = (const int*)d_in[2];
    const float* W1    = (const float*)d_in[3];
    const float* as1   = (const float*)d_in[4];
    const float* ad1   = (const float*)d_in[5];
    const float* b1    = (const float*)d_in[6];
    const float* W2    = (const float*)d_in[7];
    const float* as2   = (const float*)d_in[8];
    const float* ad2   = (const float*)d_in[9];
    const float* b2    = (const float*)d_in[10];

    float* out       = (float*)d_out;
    float* pooled    = out;              // [64, 128]
    float* alpha_out = out + GG * CC;    // [170000, 10]

    float *p_h1, *p_out1, *p_h2, *p_h2p, *p_out2;
    cudaGetSymbolAddress((void**)&p_h1,   g_h1);
    cudaGetSymbolAddress((void**)&p_out1, g_out1);
    cudaGetSymbolAddress((void**)&p_h2,   g_h2);
    cudaGetSymbolAddress((void**)&p_h2p,  g_h2p);
    cudaGetSymbolAddress((void**)&p_out2, g_out2);

    // CSR build
    k_zero_deg  <<<(NN + 255) / 256, 256>>>();
    k_prep_count<<<(ET + 255) / 256, 256>>>(ei);
    k_scan      <<<1, 1024>>>();
    k_scatter   <<<(ET + 255) / 256, 256>>>();

    // ---- layer 1 (H=10) ----
    k_gemm1<<<dim3((NN + 127) / 128, HH), 256>>>(x, W1, p_h1, as1, ad1);
    k_agg1<<<NN, 320>>>(p_h1, b1, p_out1, alpha_out);

    // ---- layer 2 (H=1) ----
    k_gemm2p<<<dim3((NN + 127) / 128, 1, 4), 256>>>(p_out1, W2, p_h2p);
    k_finish2<<<(NN + 7) / 8, 256>>>(p_h2, as2, ad2);
    k_agg2<<<(NN + 7) / 8, 256>>>(p_h2, b2, p_out2, pooled);

    // ---- global max pool ----
    k_pool<<<(NN * CC + 255) / 256, 256>>>(p_out2, batch, pooled);
}

// round 9
// speedup vs baseline: 3.7008x; 1.3457x over previous
#include <cuda_runtime.h>
#include <cuda_fp16.h>
#include <math.h>

#define NN   10000
#define EE   160000
#define ET   170000
#define FIN  78
#define CC   128
#define HH   10
#define F1   1280
#define GG   64
#define MAXD 128

#define NEG_INF __int_as_float(0xff800000)

// ---------------- scratch ----------------
__device__ __align__(16) __half g_h1h[(size_t)NN * F1];     // h1 in fp16 (gather copy)
__device__ __align__(16) float g_out1[(size_t)NN * F1];
__device__ __align__(16) float g_h2[(size_t)NN * CC];
__device__ __align__(16) float g_h2p[(size_t)4 * NN * CC];
__device__ __align__(16) float g_out2[(size_t)NN * CC];
__device__ float g_asrc[NN * HH];
__device__ float g_adst[NN * HH];
__device__ int   g_src[ET];
__device__ int   g_dst[ET];
__device__ int   g_deg[NN];
__device__ int   g_rowptr[NN + 1];
__device__ int   g_cursor[NN];
__device__ int   g_eid[ET];

__device__ __forceinline__ void atomicMaxF(float* addr, float v) {
    if (v >= 0.f) atomicMax((int*)addr, __float_as_int(v));
    else          atomicMin((unsigned int*)addr, __float_as_uint(v));
}

__device__ __forceinline__ float lrelu(float v) {
    return (v >= 0.f) ? v : 0.2f * v;
}

__device__ __forceinline__ unsigned f2tf(float f) {
    unsigned r;
    asm("cvt.rna.tf32.f32 %0, %1;" : "=r"(r) : "f"(f));
    return r;
}

// ---------------- CSR build ----------------
__global__ void k_zero_deg() {
    int i = blockIdx.x * blockDim.x + threadIdx.x;
    if (i < NN) g_deg[i] = 0;
}

__global__ void k_prep_count(const int* __restrict__ ei) {
    int i = blockIdx.x * blockDim.x + threadIdx.x;
    if (i >= ET) return;
    int s, d;
    if (i < EE) { s = ei[i]; d = ei[EE + i]; }
    else        { s = d = i - EE; }
    g_src[i] = s;
    g_dst[i] = d;
    atomicAdd(&g_deg[d], 1);
}

__global__ void k_scan() {
    __shared__ int wsum[32];
    __shared__ int carry;
    int tid = threadIdx.x, lane = tid & 31, wid = tid >> 5;
    if (tid == 0) carry = 0;
    __syncthreads();
    for (int base = 0; base < NN; base += 1024) {
        int i = base + tid;
        int v = (i < NN) ? g_deg[i] : 0;
        int x = v;
        #pragma unroll
        for (int o = 1; o < 32; o <<= 1) {
            int t = __shfl_up_sync(0xffffffff, x, o);
            if (lane >= o) x += t;
        }
        if (lane == 31) wsum[wid] = x;
        __syncthreads();
        if (wid == 0) {
            int s = wsum[lane];
            #pragma unroll
            for (int o = 1; o < 32; o <<= 1) {
                int t = __shfl_up_sync(0xffffffff, s, o);
                if (lane >= o) s += t;
            }
            wsum[lane] = s;
        }
        __syncthreads();
        int excl = carry + (wid ? wsum[wid - 1] : 0) + x - v;
        if (i < NN) { g_rowptr[i] = excl; g_cursor[i] = excl; }
        __syncthreads();
        if (tid == 0) carry += wsum[31];
        __syncthreads();
    }
    if (threadIdx.x == 0) g_rowptr[NN] = carry;
}

__global__ void k_scatter() {
    int i = blockIdx.x * blockDim.x + threadIdx.x;
    if (i >= ET) return;
    int pos = atomicAdd(&g_cursor[g_dst[i]], 1);
    g_eid[pos] = i;
}

// ------- GEMM1: x@W1 fp32 (128x128, 8x8/thr) + dots; h1 stored as fp16 ------
__global__ void __launch_bounds__(256) k_gemm1(const float* __restrict__ A,
                                               const float* __restrict__ B,
                                               const float* __restrict__ wsrc,
                                               const float* __restrict__ wdst) {
    const int M = NN, K = FIN, Nn = F1;
    __shared__ float As[16][132];
    __shared__ float Bs[16][128];
    int tid = threadIdx.x;
    int tx = tid & 15, ty = tid >> 4;
    int bm0 = blockIdx.x * 128;
    int head = blockIdx.y;
    int bn0 = head * 128;
    float acc[8][8];
    #pragma unroll
    for (int i = 0; i < 8; i++)
        #pragma unroll
        for (int j = 0; j < 8; j++) acc[i][j] = 0.f;

    for (int k0 = 0; k0 < K; k0 += 16) {
        int kk = tid & 15, r0 = tid >> 4;
        int gk = k0 + kk;
        bool kok = gk < K;
        #pragma unroll
        for (int u = 0; u < 8; u++) {
            int r = r0 + u * 16;
            int gr = bm0 + r;
            As[kk][r] = (kok && gr < M) ? A[(size_t)gr * K + gk] : 0.f;
        }
        #pragma unroll
        for (int p = 0; p < 2; p++) {
            int f = tid + p * 256;
            int k = f >> 5, n = (f & 31) * 4;
            int gk2 = k0 + k;
            float4 v = make_float4(0.f, 0.f, 0.f, 0.f);
            if (gk2 < K) v = *(const float4*)&B[(size_t)gk2 * Nn + bn0 + n];
            *(float4*)&Bs[k][n] = v;
        }
        __syncthreads();
        #pragma unroll
        for (int k = 0; k < 16; k++) {
            float a[8], b[8];
            *(float4*)&a[0] = *(const float4*)&As[k][ty * 8];
            *(float4*)&a[4] = *(const float4*)&As[k][ty * 8 + 4];
            *(float4*)&b[0] = *(const float4*)&Bs[k][tx * 8];
            *(float4*)&b[4] = *(const float4*)&Bs[k][tx * 8 + 4];
            #pragma unroll
            for (int i = 0; i < 8; i++)
                #pragma unroll
                for (int j = 0; j < 8; j++) acc[i][j] += a[i] * b[j];
        }
        __syncthreads();
    }
    float ws[8], wd[8];
    #pragma unroll
    for (int j = 0; j < 8; j++) {
        ws[j] = wsrc[head * CC + tx * 8 + j];
        wd[j] = wdst[head * CC + tx * 8 + j];
    }
    #pragma unroll
    for (int i = 0; i < 8; i++) {
        int gr = bm0 + ty * 8 + i;
        bool ok = gr < M;
        if (ok) {
            __half2 hp[4];
            hp[0] = __floats2half2_rn(acc[i][0], acc[i][1]);
            hp[1] = __floats2half2_rn(acc[i][2], acc[i][3]);
            hp[2] = __floats2half2_rn(acc[i][4], acc[i][5]);
            hp[3] = __floats2half2_rn(acc[i][6], acc[i][7]);
            *(uint4*)&g_h1h[(size_t)gr * F1 + bn0 + tx * 8] = *(uint4*)hp;
        }
        float s1 = 0.f, s2 = 0.f;
        #pragma unroll
        for (int j = 0; j < 8; j++) { s1 += acc[i][j] * ws[j]; s2 += acc[i][j] * wd[j]; }
        #pragma unroll
        for (int o = 8; o > 0; o >>= 1) {
            s1 += __shfl_down_sync(0xffffffffu, s1, o);
            s2 += __shfl_down_sync(0xffffffffu, s2, o);
        }
        if (tx == 0 && ok) {
            g_asrc[gr * HH + head] = s1;
            g_adst[gr * HH + head] = s2;
        }
    }
}

// ------- GEMM2: tf32 mma.sync, split-K=4 partials --------------------------
__global__ void __launch_bounds__(256) k_gemm2t(const float* __restrict__ A,
                                                const float* __restrict__ B,
                                                float* __restrict__ Cp) {
    const int M = NN, K = F1, Nn = CC, KS = F1 / 4;
    __shared__ unsigned As[128][20];   // [m][k], conflict-free frag loads
    __shared__ unsigned Bs[128][25];   // [n][k]
    int tid = threadIdx.x;
    int lane = tid & 31, wid = tid >> 5;
    int wm = wid & 3, wn = wid >> 2;          // 4 (m) x 2 (n) warps
    int g = lane >> 2, t = lane & 3;
    int bm0 = blockIdx.x * 128;
    int z = blockIdx.z;
    float* C = Cp + (size_t)z * M * Nn;
    float acc[2][8][4];
    #pragma unroll
    for (int mt = 0; mt < 2; mt++)
        #pragma unroll
        for (int nt = 0; nt < 8; nt++)
            #pragma unroll
            for (int q = 0; q < 4; q++) acc[mt][nt][q] = 0.f;

    int kbeg = z * KS;
    for (int k0 = kbeg; k0 < kbeg + KS; k0 += 16) {
        #pragma unroll
        for (int hh = 0; hh < 2; hh++) {
            int m = (tid >> 2) + hh * 64;
            int kq = (tid & 3) * 4;
            int gm = bm0 + m;
            float4 v = (gm < M) ? *(const float4*)&A[(size_t)gm * K + k0 + kq]
                                : make_float4(0.f, 0.f, 0.f, 0.f);
            As[m][kq + 0] = f2tf(v.x); As[m][kq + 1] = f2tf(v.y);
            As[m][kq + 2] = f2tf(v.z); As[m][kq + 3] = f2tf(v.w);
        }
        #pragma unroll
        for (int p = 0; p < 2; p++) {
            int f = tid + p * 256;
            int k = f >> 5, n = (f & 31) * 4;
            float4 v = *(const float4*)&B[(size_t)(k0 + k) * Nn + n];
            Bs[n + 0][k] = f2tf(v.x); Bs[n + 1][k] = f2tf(v.y);
            Bs[n + 2][k] = f2tf(v.z); Bs[n + 3][k] = f2tf(v.w);
        }
        __syncthreads();
        #pragma unroll
        for (int ks = 0; ks < 2; ks++) {
            int k8 = ks * 8;
            unsigned af[2][4];
            #pragma unroll
            for (int mt = 0; mt < 2; mt++) {
                int rb = wm * 32 + mt * 16;
                af[mt][0] = As[rb + g][k8 + t];
                af[mt][1] = As[rb + g + 8][k8 + t];
                af[mt][2] = As[rb + g][k8 + t + 4];
                af[mt][3] = As[rb + g + 8][k8 + t + 4];
            }
            #pragma unroll
            for (int nt = 0; nt < 8; nt++) {
                int nb = wn * 64 + nt * 8;
                unsigned b0 = Bs[nb + g][k8 + t];
                unsigned b1 = Bs[nb + g][k8 + t + 4];
                #pragma unroll
                for (int mt = 0; mt < 2; mt++) {
                    asm volatile(
                        "mma.sync.aligned.m16n8k8.row.col.f32.tf32.tf32.f32 "
                        "{%0,%1,%2,%3}, {%4,%5,%6,%7}, {%8,%9}, {%0,%1,%2,%3};"
                        : "+f"(acc[mt][nt][0]), "+f"(acc[mt][nt][1]),
                          "+f"(acc[mt][nt][2]), "+f"(acc[mt][nt][3])
                        : "r"(af[mt][0]), "r"(af[mt][1]),
                          "r"(af[mt][2]), "r"(af[mt][3]),
                          "r"(b0), "r"(b1));
                }
            }
        }
        __syncthreads();
    }
    #pragma unroll
    for (int mt = 0; mt < 2; mt++) {
        int r0 = bm0 + wm * 32 + mt * 16 + g;
        #pragma unroll
        for (int nt = 0; nt < 8; nt++) {
            int c0 = wn * 64 + nt * 8 + 2 * t;
            if (r0 < M) {
                float2 v0 = {acc[mt][nt][0], acc[mt][nt][1]};
                *(float2*)&C[(size_t)r0 * Nn + c0] = v0;
            }
            if (r0 + 8 < M) {
                float2 v1 = {acc[mt][nt][2], acc[mt][nt][3]};
                *(float2*)&C[(size_t)(r0 + 8) * Nn + c0] = v1;
            }
        }
    }
}

// ------- finish layer-2 pre-agg: sum partials + attention dots --------------
__global__ void k_finish2(float* __restrict__ h2,
                          const float* __restrict__ ws,
                          const float* __restrict__ wd) {
    int n = blockIdx.x * 8 + (threadIdx.x >> 5);
    int lane = threadIdx.x & 31;
    if (n >= NN) return;
    const float4* p4 = (const float4*)g_h2p;
    float4 v = p4[(size_t)n * 32 + lane];
    #pragma unroll
    for (int z = 1; z < 4; z++) {
        float4 t = p4[(size_t)z * NN * 32 + (size_t)n * 32 + lane];
        v.x += t.x; v.y += t.y; v.z += t.z; v.w += t.w;
    }
    ((float4*)h2)[(size_t)n * 32 + lane] = v;
    float4 w1 = ((const float4*)ws)[lane];
    float4 w2 = ((const float4*)wd)[lane];
    float s1 = v.x * w1.x + v.y * w1.y + v.z * w1.z + v.w * w1.w;
    float s2 = v.x * w2.x + v.y * w2.y + v.z * w2.z + v.w * w2.w;
    #pragma unroll
    for (int o = 16; o > 0; o >>= 1) {
        s1 += __shfl_down_sync(0xffffffffu, s1, o);
        s2 += __shfl_down_sync(0xffffffffu, s2, o);
    }
    if (lane == 0) { g_asrc[n] = s1; g_adst[n] = s2; }
}

// ----- layer-1: fused softmax (warp per head) + fp16 aggregate + bias + elu -
__global__ void __launch_bounds__(320) k_agg1(const float* __restrict__ bias,
                                              float* __restrict__ out,
                                              float* __restrict__ alpha_out) {
    __shared__ float s_alpha[HH][MAXD];
    __shared__ int   s_src[MAXD];
    __shared__ float s_mx[HH], s_inv[HH];
    int n = blockIdx.x;
    int tid = threadIdx.x, lane = tid & 31, w = tid >> 5;
    int start = g_rowptr[n];
    int deg = g_rowptr[n + 1] - start;
    bool fast = (deg <= MAXD);
    float adst_h = g_adst[n * HH + w];

    float mx = NEG_INF;
    for (int i = lane; i < deg; i += 32) {
        int eid = g_eid[start + i];
        int s = g_src[eid];
        if (w == 0 && fast) s_src[i] = s;
        float e = lrelu(g_asrc[s * HH + w] + adst_h);
        mx = fmaxf(mx, e);
    }
    #pragma unroll
    for (int o = 16; o > 0; o >>= 1) mx = fmaxf(mx, __shfl_xor_sync(0xffffffffu, mx, o));
    float sm = 0.f;
    for (int i = lane; i < deg; i += 32) {
        int eid = g_eid[start + i];
        int s = g_src[eid];
        float e = lrelu(g_asrc[s * HH + w] + adst_h);
        float ex = __expf(e - mx);
        if (fast) s_alpha[w][i] = ex;
        sm += ex;
    }
    #pragma unroll
    for (int o = 16; o > 0; o >>= 1) sm += __shfl_xor_sync(0xffffffffu, sm, o);
    float inv = __fdividef(1.f, sm + 1e-16f);
    for (int i = lane; i < deg; i += 32) {
        int eid = g_eid[start + i];
        float ex;
        if (fast) ex = s_alpha[w][i];
        else {
            int s = g_src[eid];
            ex = __expf(lrelu(g_asrc[s * HH + w] + adst_h) - mx);
        }
        float a = ex * inv;
        if (fast) s_alpha[w][i] = a;
        alpha_out[(size_t)eid * HH + w] = a;
    }
    if (lane == 0) { s_mx[w] = mx; s_inv[w] = inv; }
    __syncthreads();

    // aggregate from fp16 copy: each thread owns 4 floats = one uint2 of halfs
    float4 acc = {0.f, 0.f, 0.f, 0.f};
    const uint2* h2p = (const uint2*)g_h1h;
    if (fast) {
        for (int i = 0; i < deg; i++) {
            float al = s_alpha[w][i];
            int s = s_src[i];
            uint2 u = __ldg(h2p + (size_t)s * (F1 / 4) + tid);
            float2 f0 = __half22float2(*(__half2*)&u.x);
            float2 f1 = __half22float2(*(__half2*)&u.y);
            acc.x += f0.x * al; acc.y += f0.y * al;
            acc.z += f1.x * al; acc.w += f1.y * al;
        }
    } else {
        float mxw = s_mx[w], invw = s_inv[w];
        for (int i = 0; i < deg; i++) {
            int eid = g_eid[start + i];
            int s = g_src[eid];
            float al = __expf(lrelu(g_asrc[s * HH + w] + adst_h) - mxw) * invw;
            uint2 u = __ldg(h2p + (size_t)s * (F1 / 4) + tid);
            float2 f0 = __half22float2(*(__half2*)&u.x);
            float2 f1 = __half22float2(*(__half2*)&u.y);
            acc.x += f0.x * al; acc.y += f0.y * al;
            acc.z += f1.x * al; acc.w += f1.y * al;
        }
    }
    float4 bb = __ldg(&((const float4*)bias)[tid]);
    acc.x += bb.x; acc.y += bb.y; acc.z += bb.z; acc.w += bb.w;
    acc.x = (acc.x > 0.f) ? acc.x : expm1f(acc.x);
    acc.y = (acc.y > 0.f) ? acc.y : expm1f(acc.y);
    acc.z = (acc.z > 0.f) ? acc.z : expm1f(acc.z);
    acc.w = (acc.w > 0.f) ? acc.w : expm1f(acc.w);
    ((float4*)out)[(size_t)n * (F1 / 4) + tid] = acc;
}

// ----- layer-2: fused softmax + aggregate + bias + elu + pool init ----------
__global__ void __launch_bounds__(256) k_agg2(const float* __restrict__ h,
                                              const float* __restrict__ bias,
                                              float* __restrict__ out,
                                              float* __restrict__ pooled) {
    __shared__ float s_ex[8][MAXD];
    __shared__ int   s_src[8][MAXD];
    int gidx = blockIdx.x * 256 + threadIdx.x;
    if (gidx < GG * CC) pooled[gidx] = NEG_INF;
    int wl = threadIdx.x >> 5;
    int lane = threadIdx.x & 31;
    int n = blockIdx.x * 8 + wl;
    if (n >= NN) return;
    int start = g_rowptr[n];
    int deg = g_rowptr[n + 1] - start;
    bool fast = (deg <= MAXD);
    float adst = g_adst[n];

    float mx = NEG_INF;
    for (int i = lane; i < deg; i += 32) {
        int eid = g_eid[start + i];
        int s = g_src[eid];
        if (fast) s_src[wl][i] = s;
        float e = lrelu(g_asrc[s] + adst);
        mx = fmaxf(mx, e);
    }
    #pragma unroll
    for (int o = 16; o > 0; o >>= 1) mx = fmaxf(mx, __shfl_xor_sync(0xffffffffu, mx, o));
    float sm = 0.f;
    for (int i = lane; i < deg; i += 32) {
        int eid = g_eid[start + i];
        int s = g_src[eid];
        float ex = __expf(lrelu(g_asrc[s] + adst) - mx);
        if (fast) s_ex[wl][i] = ex;
        sm += ex;
    }
    #pragma unroll
    for (int o = 16; o > 0; o >>= 1) sm += __shfl_xor_sync(0xffffffffu, sm, o);
    float inv = __fdividef(1.f, sm + 1e-16f);

    float4 acc = {0.f, 0.f, 0.f, 0.f};
    const float4* h4 = (const float4*)h;
    if (fast) {
        for (int i = 0; i < deg; i++) {
            float al = s_ex[wl][i] * inv;
            int s = s_src[wl][i];
            float4 v = __ldg(&h4[(size_t)s * 32 + lane]);
            acc.x += v.x * al; acc.y += v.y * al;
            acc.z += v.z * al; acc.w += v.w * al;
        }
    } else {
        for (int i = 0; i < deg; i++) {
            int eid = g_eid[start + i];
            int s = g_src[eid];
            float al = __expf(lrelu(g_asrc[s] + adst) - mx) * inv;
            float4 v = __ldg(&h4[(size_t)s * 32 + lane]);
            acc.x += v.x * al; acc.y += v.y * al;
            acc.z += v.z * al; acc.w += v.w * al;
        }
    }
    float4 bb = __ldg(&((const float4*)bias)[lane]);
    acc.x += bb.x; acc.y += bb.y; acc.z += bb.z; acc.w += bb.w;
    acc.x = (acc.x > 0.f) ? acc.x : expm1f(acc.x);
    acc.y = (acc.y > 0.f) ? acc.y : expm1f(acc.y);
    acc.z = (acc.z > 0.f) ? acc.z : expm1f(acc.z);
    acc.w = (acc.w > 0.f) ? acc.w : expm1f(acc.w);
    ((float4*)out)[(size_t)n * 32 + lane] = acc;
}

__global__ void k_pool(const float* __restrict__ h2a,
                       const int* __restrict__ batch,
                       float* __restrict__ out) {
    int i = blockIdx.x * blockDim.x + threadIdx.x;
    if (i >= NN * CC) return;
    int n = i >> 7, c = i & 127;
    int g = batch[n];
    atomicMaxF(&out[g * CC + c], h2a[i]);
}

// ---------------- launch ----------------
extern "C" void kernel_launch(void* const* d_in, const int* in_sizes, int n_in,
                              void* d_out, int out_size) {
    const float* x     = (const float*)d_in[0];
    const int*   ei    = (const int*)d_in[1];
    const int*   batch = (const int*)d_in[2];
    const float* W1    = (const float*)d_in[3];
    const float* as1   = (const float*)d_in[4];
    const float* ad1   = (const float*)d_in[5];
    const float* b1    = (const float*)d_in[6];
    const float* W2    = (const float*)d_in[7];
    const float* as2   = (const float*)d_in[8];
    const float* ad2   = (const float*)d_in[9];
    const float* b2    = (const float*)d_in[10];

    float* out       = (float*)d_out;
    float* pooled    = out;              // [64, 128]
    float* alpha_out = out + GG * CC;    // [170000, 10]

    float *p_out1, *p_h2, *p_h2p, *p_out2;
    cudaGetSymbolAddress((void**)&p_out1, g_out1);
    cudaGetSymbolAddress((void**)&p_h2,   g_h2);
    cudaGetSymbolAddress((void**)&p_h2p,  g_h2p);
    cudaGetSymbolAddress((void**)&p_out2, g_out2);

    // CSR build
    k_zero_deg  <<<(NN + 255) / 256, 256>>>();
    k_prep_count<<<(ET + 255) / 256, 256>>>(ei);
    k_scan      <<<1, 1024>>>();
    k_scatter   <<<(ET + 255) / 256, 256>>>();

    // ---- layer 1 (H=10) ----
    k_gemm1<<<dim3((NN + 127) / 128, HH), 256>>>(x, W1, as1, ad1);
    k_agg1<<<NN, 320>>>(b1, p_out1, alpha_out);

    // ---- layer 2 (H=1) ----
    k_gemm2t<<<dim3((NN + 127) / 128, 1, 4), 256>>>(p_out1, W2, p_h2p);
    k_finish2<<<(NN + 7) / 8, 256>>>(p_h2, as2, ad2);
    k_agg2<<<(NN + 7) / 8, 256>>>(p_h2, b2, p_out2, pooled);

    // ---- global max pool ----
    k_pool<<<(NN * CC + 255) / 256, 256>>>(p_out2, batch, pooled);
}